// round 10
// baseline (speedup 1.0000x reference)
#include <cuda_runtime.h>
#include <math.h>

#define S_SEG 256
#define T_TOK 512
#define BERT  768
#define POSD  128
#define CAT   (BERT + POSD)   // 896
#define H1    1024
#define NCLS  6
#define NSEG  64
#define KSLICES 32
#define TOKW    16                       // tokens per warp
#define WSLICES (T_TOK / TOKW)           // 32 warp-slices per segment

// Scratch (no allocations allowed) — device globals.
__device__ float g_pacc[WSLICES * S_SEG * BERT];   // unnormalized partial accumulators
__device__ float g_pm[WSLICES * S_SEG];            // partial max
__device__ float g_pd[WSLICES * S_SEG];            // partial denom
__device__ float g_segvec[S_SEG * BERT];
__device__ float g_vecs[NSEG * BERT];
__device__ float g_h1[NSEG * H1];
__device__ float g_h2[NSEG * H1];
__device__ float g_part[KSLICES * NSEG * H1];

// ---------------------------------------------------------------------------
// Kernel 1a: warp-per-token online-softmax pooling, TWO tokens per iteration
// (amortizes the shfl-reduce + exp chain; 14 loads in flight per phase).
// grid (256, 4) = 1024 CTAs. Warp (s, q*8+wid) handles 16 tokens.
// ---------------------------------------------------------------------------
__global__ __launch_bounds__(256, 2)
void pool_part_kernel(const float* __restrict__ emb,
                      const float* __restrict__ pos,
                      const float* __restrict__ Wa,
                      const float* __restrict__ ba)
{
    __shared__ float s_wa[CAT];
    const int s    = blockIdx.x;
    const int q    = blockIdx.y;
    const int tid  = threadIdx.x;
    const int wid  = tid >> 5;
    const int lane = tid & 31;

    for (int i = tid; i < CAT; i += 256) s_wa[i] = Wa[i];
    __syncthreads();   // only barrier in the kernel

    const int   slice = q * 8 + wid;
    const int   t0    = slice * TOKW;
    const float bias  = ba[0];

    const float* eb = emb + (size_t)s * T_TOK * BERT;
    const float* pb = pos + (size_t)s * T_TOK * POSD;

    float4 acc[6];
    #pragma unroll
    for (int i = 0; i < 6; i++) acc[i] = make_float4(0.f, 0.f, 0.f, 0.f);
    float m = -1e30f;
    float d = 0.f;

    #pragma unroll 1
    for (int j = 0; j < TOKW; j += 2) {
        const int t = t0 + j;

        // issue both tokens' loads up front (14 LDG.128 in flight)
        float4 x0[7], x1[7];
        #pragma unroll
        for (int i = 0; i < 6; i++)
            x0[i] = *(const float4*)(eb + (size_t)t * BERT + i * 128 + lane * 4);
        x0[6] = *(const float4*)(pb + (size_t)t * POSD + lane * 4);
        #pragma unroll
        for (int i = 0; i < 6; i++)
            x1[i] = *(const float4*)(eb + (size_t)(t + 1) * BERT + i * 128 + lane * 4);
        x1[6] = *(const float4*)(pb + (size_t)(t + 1) * POSD + lane * 4);

        float p0 = 0.f, p1 = 0.f;
        #pragma unroll
        for (int i = 0; i < 7; i++) {
            const float4 wv = *(const float4*)(s_wa + i * 128 + lane * 4);
            p0 += x0[i].x * wv.x + x0[i].y * wv.y + x0[i].z * wv.z + x0[i].w * wv.w;
            p1 += x1[i].x * wv.x + x1[i].y * wv.y + x1[i].z * wv.z + x1[i].w * wv.w;
        }
        #pragma unroll
        for (int o = 16; o > 0; o >>= 1) {
            p0 += __shfl_xor_sync(0xffffffffu, p0, o);
            p1 += __shfl_xor_sync(0xffffffffu, p1, o);
        }

        const float a0    = p0 + bias;
        const float a1    = p1 + bias;
        const float m_new = fmaxf(m, fmaxf(a0, a1));
        const float scale = __expf(m - m_new);
        const float e0    = __expf(a0 - m_new);
        const float e1    = __expf(a1 - m_new);
        d = d * scale + e0 + e1;
        #pragma unroll
        for (int i = 0; i < 6; i++) {
            acc[i].x = acc[i].x * scale + e0 * x0[i].x + e1 * x1[i].x;
            acc[i].y = acc[i].y * scale + e0 * x0[i].y + e1 * x1[i].y;
            acc[i].z = acc[i].z * scale + e0 * x0[i].z + e1 * x1[i].z;
            acc[i].w = acc[i].w * scale + e0 * x0[i].w + e1 * x1[i].w;
        }
        m = m_new;
    }

    const int ps = slice * S_SEG + s;
    float* ob = g_pacc + (size_t)ps * BERT;
    #pragma unroll
    for (int i = 0; i < 6; i++)
        *(float4*)(ob + i * 128 + lane * 4) = acc[i];
    if (lane == 0) {
        g_pm[ps] = m;
        g_pd[ps] = d;
    }
}

// ---------------------------------------------------------------------------
// Kernel 1b: merge WSLICES=32 partials per segment (flash-attn merge).
// ---------------------------------------------------------------------------
__global__ __launch_bounds__(192)
void pool_merge_kernel()
{
    __shared__ float sm[WSLICES], sd[WSLICES], ssc[WSLICES];
    const int s   = blockIdx.x;
    const int tid = threadIdx.x;

    if (tid < WSLICES) {
        sm[tid] = g_pm[tid * S_SEG + s];
        sd[tid] = g_pd[tid * S_SEG + s];
    }
    __syncthreads();

    float M = -1e30f;
    #pragma unroll
    for (int z = 0; z < WSLICES; z++) M = fmaxf(M, sm[z]);

    if (tid < WSLICES) ssc[tid] = __expf(sm[tid] - M);
    __syncthreads();

    float D = 0.f;
    #pragma unroll
    for (int z = 0; z < WSLICES; z++) D += sd[z] * ssc[z];
    const float inv = 1.f / D;

    float4 acc = make_float4(0.f, 0.f, 0.f, 0.f);
    #pragma unroll 4
    for (int z = 0; z < WSLICES; z++) {
        const float  f = ssc[z];
        const float4 p = *(const float4*)(g_pacc + (size_t)(z * S_SEG + s) * BERT + 4 * tid);
        acc.x += f * p.x;
        acc.y += f * p.y;
        acc.z += f * p.z;
        acc.w += f * p.w;
    }
    float4 o = make_float4(acc.x * inv, acc.y * inv, acc.z * inv, acc.w * inv);
    *(float4*)(g_segvec + (size_t)s * BERT + 4 * tid) = o;
}

// ---------------------------------------------------------------------------
// Kernel 2: deterministic segment sum (sorted ids). One CTA per segment g.
// ---------------------------------------------------------------------------
__global__ __launch_bounds__(256)
void segsum_kernel(const int* __restrict__ seg)
{
    __shared__ int sid[S_SEG];
    const int g = blockIdx.x;
    const int tid = threadIdx.x;
    sid[tid] = seg[tid];
    __syncthreads();

    float a0 = 0.f, a1 = 0.f, a2 = 0.f;
    for (int s = 0; s < S_SEG; s++) {
        if (sid[s] == g) {
            const float* r = g_segvec + (size_t)s * BERT;
            a0 += r[tid];
            a1 += r[tid + 256];
            a2 += r[tid + 512];
        }
    }
    g_vecs[g * BERT + tid]       = a0;
    g_vecs[g * BERT + tid + 256] = a1;
    g_vecs[g * BERT + tid + 512] = a2;
}

// ---------------------------------------------------------------------------
// Kernels 3/4: split-K GEMM partials with 8-deep register prefetch.
// grid (16 colblocks, 4 rowblocks, KSLICES=32) = 2048 CTAs, 128 threads.
// CTA = 16 rows x 64 cols x CHUNK. thread = (colquad q -> 4 cols,
// rowgroup r -> 2 rows). CHUNK = 24 (K=768) / 32 (K=1024).
// ---------------------------------------------------------------------------
template <int K>
__global__ __launch_bounds__(128)
void mlp_splitk_kernel(const float* __restrict__ in, const float* __restrict__ W,
                       float* __restrict__ part)
{
    constexpr int CHUNK = K / KSLICES;   // 24 or 32 (multiples of 8)
    constexpr int NB    = CHUNK / 8;     // 3 or 4 batches
    constexpr int TP    = CHUNK + 1;
    __shared__ float tile[16 * TP];

    const int tid   = threadIdx.x;
    const int q     = tid & 15;
    const int r     = tid >> 4;          // 0..7
    const int jbase = blockIdx.x * 64 + q * 4;
    const int rbase = blockIdx.y * 16;
    const int k0    = blockIdx.z * CHUNK;

    for (int e = tid; e < 16 * CHUNK; e += 128) {
        int rr = e / CHUNK;
        int cc = e - rr * CHUNK;
        tile[rr * TP + cc] = in[(size_t)(rbase + rr) * K + k0 + cc];
    }
    __syncthreads();

    float4 acc[2];
    acc[0] = make_float4(0.f, 0.f, 0.f, 0.f);
    acc[1] = make_float4(0.f, 0.f, 0.f, 0.f);

    const float* wp = W + (size_t)k0 * H1 + jbase;
    const float* xp = tile + (r * 2) * TP;

    float4 wbuf[8];
    #pragma unroll
    for (int i = 0; i < 8; i++)
        wbuf[i] = *(const float4*)(wp + (size_t)i * H1);

    #pragma unroll
    for (int kb = 0; kb < NB; kb++) {
        float4 wnext[8];
        if (kb + 1 < NB) {
            #pragma unroll
            for (int i = 0; i < 8; i++)
                wnext[i] = *(const float4*)(wp + (size_t)((kb + 1) * 8 + i) * H1);
        }
        #pragma unroll
        for (int i = 0; i < 8; i++) {
            const int kk = kb * 8 + i;
            #pragma unroll
            for (int rr = 0; rr < 2; rr++) {
                const float xv = xp[rr * TP + kk];
                acc[rr].x += xv * wbuf[i].x;
                acc[rr].y += xv * wbuf[i].y;
                acc[rr].z += xv * wbuf[i].z;
                acc[rr].w += xv * wbuf[i].w;
            }
        }
        if (kb + 1 < NB) {
            #pragma unroll
            for (int i = 0; i < 8; i++) wbuf[i] = wnext[i];
        }
    }

    float* pb = part + (size_t)blockIdx.z * NSEG * H1 + (size_t)(rbase + r * 2) * H1 + jbase;
    *(float4*)(pb)               = acc[0];
    *(float4*)(pb + (size_t)H1)  = acc[1];
}

// Reduce partials + bias + LeakyReLU(0.01). grid 256 (quarter-row per CTA),
// 256 threads, one scalar column each. 32 independent loads per thread.
__global__ __launch_bounds__(256)
void mlp_reduce_kernel(const float* __restrict__ b, float* __restrict__ out)
{
    const int row = blockIdx.x >> 2;
    const int col = (blockIdx.x & 3) * 256 + threadIdx.x;
    const size_t off = (size_t)row * H1 + col;

    float a = 0.f;
    #pragma unroll
    for (int z = 0; z < KSLICES; z++)
        a += g_part[(size_t)z * NSEG * H1 + off];

    a += b[col];
    out[off] = a > 0.f ? a : 0.01f * a;
}

// ---------------------------------------------------------------------------
// Kernel 5: head (64,1024)@(1024,6) + bias, sigmoid. One warp per segment.
// ---------------------------------------------------------------------------
__global__ __launch_bounds__(32)
void head_kernel(const float* __restrict__ W3, const float* __restrict__ b3,
                 float* __restrict__ out)
{
    const int g    = blockIdx.x;
    const int lane = threadIdx.x;
    float p[NCLS] = {0.f, 0.f, 0.f, 0.f, 0.f, 0.f};

    for (int k = lane; k < H1; k += 32) {
        float x = g_h2[(size_t)g * H1 + k];
        #pragma unroll
        for (int j = 0; j < NCLS; j++)
            p[j] += x * W3[k * NCLS + j];
    }
    #pragma unroll
    for (int j = 0; j < NCLS; j++) {
        #pragma unroll
        for (int o = 16; o > 0; o >>= 1)
            p[j] += __shfl_xor_sync(0xffffffffu, p[j], o);
    }
    if (lane < NCLS) {
        float v = p[lane] + b3[lane];
        out[g * NCLS + lane] = 1.f / (1.f + expf(-v));
    }
}

// ---------------------------------------------------------------------------
extern "C" void kernel_launch(void* const* d_in, const int* in_sizes, int n_in,
                              void* d_out, int out_size)
{
    (void)in_sizes; (void)n_in; (void)out_size;
    const float* emb = (const float*)d_in[0];
    const float* pos = (const float*)d_in[1];
    const float* Wa  = (const float*)d_in[2];
    const float* ba  = (const float*)d_in[3];
    const float* W1  = (const float*)d_in[4];
    const float* b1  = (const float*)d_in[5];
    const float* W2  = (const float*)d_in[6];
    const float* b2  = (const float*)d_in[7];
    const float* W3  = (const float*)d_in[8];
    const float* b3  = (const float*)d_in[9];
    const int*   seg = (const int*)d_in[10];
    float* out = (float*)d_out;

    void *p_vecs = nullptr, *p_h1 = nullptr, *p_h2 = nullptr, *p_part = nullptr;
    cudaGetSymbolAddress(&p_vecs, g_vecs);
    cudaGetSymbolAddress(&p_h1, g_h1);
    cudaGetSymbolAddress(&p_h2, g_h2);
    cudaGetSymbolAddress(&p_part, g_part);

    pool_part_kernel<<<dim3(S_SEG, 4), 256>>>(emb, pos, Wa, ba);
    pool_merge_kernel<<<S_SEG, 192>>>();
    segsum_kernel<<<NSEG, 256>>>(seg);

    mlp_splitk_kernel<BERT><<<dim3(16, 4, KSLICES), 128>>>(
        (const float*)p_vecs, W1, (float*)p_part);
    mlp_reduce_kernel<<<NSEG * 4, 256>>>(b1, (float*)p_h1);

    mlp_splitk_kernel<H1><<<dim3(16, 4, KSLICES), 128>>>(
        (const float*)p_h1, W2, (float*)p_part);
    mlp_reduce_kernel<<<NSEG * 4, 256>>>(b2, (float*)p_h2);

    head_kernel<<<NSEG, 32>>>(W3, b3, out);
}

// round 11
// speedup vs baseline: 1.0746x; 1.0746x over previous
#include <cuda_runtime.h>
#include <math.h>

#define S_SEG 256
#define T_TOK 512
#define BERT  768
#define POSD  128
#define CAT   (BERT + POSD)   // 896
#define H1    1024
#define NCLS  6
#define NSEG  64
#define KSLICES 32
#define TOKW    16                       // tokens per warp
#define WSLICES (T_TOK / TOKW)           // 32 warp-slices per segment

// Scratch (no allocations allowed) — device globals.
__device__ float g_pacc[WSLICES * S_SEG * BERT];   // unnormalized partial accumulators
__device__ float g_pm[WSLICES * S_SEG];            // partial max
__device__ float g_pd[WSLICES * S_SEG];            // partial denom
__device__ float g_segvec[S_SEG * BERT];
__device__ float g_vecs[NSEG * BERT];
__device__ float g_h1[NSEG * H1];
__device__ float g_h2[NSEG * H1];
__device__ float g_part[KSLICES * NSEG * H1];

// ---------------------------------------------------------------------------
// Kernel 1a: warp-per-token online-softmax pooling, TWO tokens per iteration
// (amortizes the shfl-reduce + exp chain; 14 loads in flight per phase).
// grid (256, 4) = 1024 CTAs. Warp (s, q*8+wid) handles 16 tokens.
// ---------------------------------------------------------------------------
__global__ __launch_bounds__(256, 2)
void pool_part_kernel(const float* __restrict__ emb,
                      const float* __restrict__ pos,
                      const float* __restrict__ Wa,
                      const float* __restrict__ ba)
{
    __shared__ float s_wa[CAT];
    const int s    = blockIdx.x;
    const int q    = blockIdx.y;
    const int tid  = threadIdx.x;
    const int wid  = tid >> 5;
    const int lane = tid & 31;

    for (int i = tid; i < CAT; i += 256) s_wa[i] = Wa[i];
    __syncthreads();   // only barrier in the kernel

    const int   slice = q * 8 + wid;
    const int   t0    = slice * TOKW;
    const float bias  = ba[0];

    const float* eb = emb + (size_t)s * T_TOK * BERT;
    const float* pb = pos + (size_t)s * T_TOK * POSD;

    float4 acc[6];
    #pragma unroll
    for (int i = 0; i < 6; i++) acc[i] = make_float4(0.f, 0.f, 0.f, 0.f);
    float m = -1e30f;
    float d = 0.f;

    #pragma unroll 1
    for (int j = 0; j < TOKW; j += 2) {
        const int t = t0 + j;

        // issue both tokens' loads up front (14 LDG.128 in flight)
        float4 x0[7], x1[7];
        #pragma unroll
        for (int i = 0; i < 6; i++)
            x0[i] = *(const float4*)(eb + (size_t)t * BERT + i * 128 + lane * 4);
        x0[6] = *(const float4*)(pb + (size_t)t * POSD + lane * 4);
        #pragma unroll
        for (int i = 0; i < 6; i++)
            x1[i] = *(const float4*)(eb + (size_t)(t + 1) * BERT + i * 128 + lane * 4);
        x1[6] = *(const float4*)(pb + (size_t)(t + 1) * POSD + lane * 4);

        float p0 = 0.f, p1 = 0.f;
        #pragma unroll
        for (int i = 0; i < 7; i++) {
            const float4 wv = *(const float4*)(s_wa + i * 128 + lane * 4);
            p0 += x0[i].x * wv.x + x0[i].y * wv.y + x0[i].z * wv.z + x0[i].w * wv.w;
            p1 += x1[i].x * wv.x + x1[i].y * wv.y + x1[i].z * wv.z + x1[i].w * wv.w;
        }
        #pragma unroll
        for (int o = 16; o > 0; o >>= 1) {
            p0 += __shfl_xor_sync(0xffffffffu, p0, o);
            p1 += __shfl_xor_sync(0xffffffffu, p1, o);
        }

        const float a0    = p0 + bias;
        const float a1    = p1 + bias;
        const float m_new = fmaxf(m, fmaxf(a0, a1));
        const float scale = __expf(m - m_new);
        const float e0    = __expf(a0 - m_new);
        const float e1    = __expf(a1 - m_new);
        d = d * scale + e0 + e1;
        #pragma unroll
        for (int i = 0; i < 6; i++) {
            acc[i].x = acc[i].x * scale + e0 * x0[i].x + e1 * x1[i].x;
            acc[i].y = acc[i].y * scale + e0 * x0[i].y + e1 * x1[i].y;
            acc[i].z = acc[i].z * scale + e0 * x0[i].z + e1 * x1[i].z;
            acc[i].w = acc[i].w * scale + e0 * x0[i].w + e1 * x1[i].w;
        }
        m = m_new;
    }

    const int ps = slice * S_SEG + s;
    float* ob = g_pacc + (size_t)ps * BERT;
    #pragma unroll
    for (int i = 0; i < 6; i++)
        *(float4*)(ob + i * 128 + lane * 4) = acc[i];
    if (lane == 0) {
        g_pm[ps] = m;
        g_pd[ps] = d;
    }
}

// ---------------------------------------------------------------------------
// Kernel 1b: merge WSLICES=32 partials per segment (flash-attn merge).
// ---------------------------------------------------------------------------
__global__ __launch_bounds__(192)
void pool_merge_kernel()
{
    __shared__ float sm[WSLICES], sd[WSLICES], ssc[WSLICES];
    const int s   = blockIdx.x;
    const int tid = threadIdx.x;

    if (tid < WSLICES) {
        sm[tid] = g_pm[tid * S_SEG + s];
        sd[tid] = g_pd[tid * S_SEG + s];
    }
    __syncthreads();

    float M = -1e30f;
    #pragma unroll
    for (int z = 0; z < WSLICES; z++) M = fmaxf(M, sm[z]);

    if (tid < WSLICES) ssc[tid] = __expf(sm[tid] - M);
    __syncthreads();

    float D = 0.f;
    #pragma unroll
    for (int z = 0; z < WSLICES; z++) D += sd[z] * ssc[z];
    const float inv = 1.f / D;

    float4 acc = make_float4(0.f, 0.f, 0.f, 0.f);
    #pragma unroll 4
    for (int z = 0; z < WSLICES; z++) {
        const float  f = ssc[z];
        const float4 p = *(const float4*)(g_pacc + (size_t)(z * S_SEG + s) * BERT + 4 * tid);
        acc.x += f * p.x;
        acc.y += f * p.y;
        acc.z += f * p.z;
        acc.w += f * p.w;
    }
    float4 o = make_float4(acc.x * inv, acc.y * inv, acc.z * inv, acc.w * inv);
    *(float4*)(g_segvec + (size_t)s * BERT + 4 * tid) = o;
}

// ---------------------------------------------------------------------------
// Kernel 2: deterministic segment sum (sorted ids). One CTA per segment g.
// ---------------------------------------------------------------------------
__global__ __launch_bounds__(256)
void segsum_kernel(const int* __restrict__ seg)
{
    __shared__ int sid[S_SEG];
    const int g = blockIdx.x;
    const int tid = threadIdx.x;
    sid[tid] = seg[tid];
    __syncthreads();

    float a0 = 0.f, a1 = 0.f, a2 = 0.f;
    for (int s = 0; s < S_SEG; s++) {
        if (sid[s] == g) {
            const float* r = g_segvec + (size_t)s * BERT;
            a0 += r[tid];
            a1 += r[tid + 256];
            a2 += r[tid + 512];
        }
    }
    g_vecs[g * BERT + tid]       = a0;
    g_vecs[g * BERT + tid + 256] = a1;
    g_vecs[g * BERT + tid + 512] = a2;
}

// ---------------------------------------------------------------------------
// Kernels 3/4: split-K GEMM partials with 8-deep register prefetch.
// R9-measured-best config: grid (16 colblocks, 2 rowblocks, KSLICES=32)
// = 1024 CTAs, 128 threads. CTA = 32 rows x 64 cols x CHUNK.
// thread = (colquad q -> 4 cols, rowgroup r -> 4 rows).
// ---------------------------------------------------------------------------
template <int K>
__global__ __launch_bounds__(128)
void mlp_splitk_kernel(const float* __restrict__ in, const float* __restrict__ W,
                       float* __restrict__ part)
{
    constexpr int CHUNK = K / KSLICES;   // 24 or 32 (multiples of 8)
    constexpr int NB    = CHUNK / 8;     // 3 or 4 batches
    constexpr int TP    = CHUNK + 1;
    __shared__ float tile[32 * TP];

    const int tid   = threadIdx.x;
    const int q     = tid & 15;
    const int r     = tid >> 4;          // 0..7
    const int jbase = blockIdx.x * 64 + q * 4;
    const int rbase = blockIdx.y * 32;
    const int k0    = blockIdx.z * CHUNK;

    for (int e = tid; e < 32 * CHUNK; e += 128) {
        int rr = e / CHUNK;
        int cc = e - rr * CHUNK;
        tile[rr * TP + cc] = in[(size_t)(rbase + rr) * K + k0 + cc];
    }
    __syncthreads();

    float4 acc[4];
    #pragma unroll
    for (int i = 0; i < 4; i++) acc[i] = make_float4(0.f, 0.f, 0.f, 0.f);

    const float* wp = W + (size_t)k0 * H1 + jbase;
    const float* xp = tile + (r * 4) * TP;

    float4 wbuf[8];
    #pragma unroll
    for (int i = 0; i < 8; i++)
        wbuf[i] = *(const float4*)(wp + (size_t)i * H1);

    #pragma unroll
    for (int kb = 0; kb < NB; kb++) {
        float4 wnext[8];
        if (kb + 1 < NB) {
            #pragma unroll
            for (int i = 0; i < 8; i++)
                wnext[i] = *(const float4*)(wp + (size_t)((kb + 1) * 8 + i) * H1);
        }
        #pragma unroll
        for (int i = 0; i < 8; i++) {
            const int kk = kb * 8 + i;
            #pragma unroll
            for (int rr = 0; rr < 4; rr++) {
                const float xv = xp[rr * TP + kk];
                acc[rr].x += xv * wbuf[i].x;
                acc[rr].y += xv * wbuf[i].y;
                acc[rr].z += xv * wbuf[i].z;
                acc[rr].w += xv * wbuf[i].w;
            }
        }
        if (kb + 1 < NB) {
            #pragma unroll
            for (int i = 0; i < 8; i++) wbuf[i] = wnext[i];
        }
    }

    float* pb = part + (size_t)blockIdx.z * NSEG * H1 + (size_t)(rbase + r * 4) * H1 + jbase;
    #pragma unroll
    for (int i = 0; i < 4; i++)
        *(float4*)(pb + (size_t)i * H1) = acc[i];
}

// Reduce partials + bias + LeakyReLU(0.01). grid 256 (quarter-row per CTA),
// 256 threads, one scalar column each. 32 independent loads per thread.
__global__ __launch_bounds__(256)
void mlp_reduce_kernel(const float* __restrict__ b, float* __restrict__ out)
{
    const int row = blockIdx.x >> 2;
    const int col = (blockIdx.x & 3) * 256 + threadIdx.x;
    const size_t off = (size_t)row * H1 + col;

    float a = 0.f;
    #pragma unroll
    for (int z = 0; z < KSLICES; z++)
        a += g_part[(size_t)z * NSEG * H1 + off];

    a += b[col];
    out[off] = a > 0.f ? a : 0.01f * a;
}

// ---------------------------------------------------------------------------
// Kernel 5: head (64,1024)@(1024,6) + bias, sigmoid. One warp per segment.
// ---------------------------------------------------------------------------
__global__ __launch_bounds__(32)
void head_kernel(const float* __restrict__ W3, const float* __restrict__ b3,
                 float* __restrict__ out)
{
    const int g    = blockIdx.x;
    const int lane = threadIdx.x;
    float p[NCLS] = {0.f, 0.f, 0.f, 0.f, 0.f, 0.f};

    for (int k = lane; k < H1; k += 32) {
        float x = g_h2[(size_t)g * H1 + k];
        #pragma unroll
        for (int j = 0; j < NCLS; j++)
            p[j] += x * W3[k * NCLS + j];
    }
    #pragma unroll
    for (int j = 0; j < NCLS; j++) {
        #pragma unroll
        for (int o = 16; o > 0; o >>= 1)
            p[j] += __shfl_xor_sync(0xffffffffu, p[j], o);
    }
    if (lane < NCLS) {
        float v = p[lane] + b3[lane];
        out[g * NCLS + lane] = 1.f / (1.f + expf(-v));
    }
}

// ---------------------------------------------------------------------------
extern "C" void kernel_launch(void* const* d_in, const int* in_sizes, int n_in,
                              void* d_out, int out_size)
{
    (void)in_sizes; (void)n_in; (void)out_size;
    const float* emb = (const float*)d_in[0];
    const float* pos = (const float*)d_in[1];
    const float* Wa  = (const float*)d_in[2];
    const float* ba  = (const float*)d_in[3];
    const float* W1  = (const float*)d_in[4];
    const float* b1  = (const float*)d_in[5];
    const float* W2  = (const float*)d_in[6];
    const float* b2  = (const float*)d_in[7];
    const float* W3  = (const float*)d_in[8];
    const float* b3  = (const float*)d_in[9];
    const int*   seg = (const int*)d_in[10];
    float* out = (float*)d_out;

    void *p_vecs = nullptr, *p_h1 = nullptr, *p_h2 = nullptr, *p_part = nullptr;
    cudaGetSymbolAddress(&p_vecs, g_vecs);
    cudaGetSymbolAddress(&p_h1, g_h1);
    cudaGetSymbolAddress(&p_h2, g_h2);
    cudaGetSymbolAddress(&p_part, g_part);

    pool_part_kernel<<<dim3(S_SEG, 4), 256>>>(emb, pos, Wa, ba);
    pool_merge_kernel<<<S_SEG, 192>>>();
    segsum_kernel<<<NSEG, 256>>>(seg);

    mlp_splitk_kernel<BERT><<<dim3(16, 2, KSLICES), 128>>>(
        (const float*)p_vecs, W1, (float*)p_part);
    mlp_reduce_kernel<<<NSEG * 4, 256>>>(b1, (float*)p_h1);

    mlp_splitk_kernel<H1><<<dim3(16, 2, KSLICES), 128>>>(
        (const float*)p_h1, W2, (float*)p_part);
    mlp_reduce_kernel<<<NSEG * 4, 256>>>(b2, (float*)p_h2);

    head_kernel<<<NSEG, 32>>>(W3, b3, out);
}

// round 13
// speedup vs baseline: 1.1242x; 1.0461x over previous
#include <cuda_runtime.h>
#include <cstdint>
#include <math.h>

#define S_SEG 256
#define T_TOK 512
#define BERT  768
#define POSD  128
#define CAT   (BERT + POSD)   // 896
#define H1    1024
#define NCLS  6
#define NSEG  64
#define KSLICES 32
#define TOKW    16                       // tokens per warp
#define WSLICES (T_TOK / TOKW)           // 32 warp-slices per segment

// Scratch (no allocations allowed) — device globals.
__device__ float g_pacc[WSLICES * S_SEG * BERT];   // unnormalized partial accumulators
__device__ float g_pm[WSLICES * S_SEG];            // partial max
__device__ float g_pd[WSLICES * S_SEG];            // partial denom
__device__ float g_segvec[S_SEG * BERT];
__device__ float g_vecs[NSEG * BERT];
__device__ float g_h1[NSEG * H1];
__device__ float g_h2[NSEG * H1];
__device__ float g_part[KSLICES * NSEG * H1];

#define CP_ASYNC_16(dst_u32, src_ptr) \
    asm volatile("cp.async.cg.shared.global [%0], [%1], 16;" \
                 :: "r"(dst_u32), "l"(src_ptr) : "memory")
#define CP_ASYNC_WAIT_ALL() \
    asm volatile("cp.async.commit_group;\n\tcp.async.wait_group 0;" ::: "memory")

// ---------------------------------------------------------------------------
// Kernel 1a: warp-per-token online-softmax pooling, TWO tokens per iteration
// (amortizes the shfl-reduce + exp chain; 14 loads in flight per phase).
// grid (256, 4) = 1024 CTAs. Warp (s, q*8+wid) handles 16 tokens.
// ---------------------------------------------------------------------------
__global__ __launch_bounds__(256, 2)
void pool_part_kernel(const float* __restrict__ emb,
                      const float* __restrict__ pos,
                      const float* __restrict__ Wa,
                      const float* __restrict__ ba)
{
    __shared__ float s_wa[CAT];
    const int s    = blockIdx.x;
    const int q    = blockIdx.y;
    const int tid  = threadIdx.x;
    const int wid  = tid >> 5;
    const int lane = tid & 31;

    for (int i = tid; i < CAT; i += 256) s_wa[i] = Wa[i];
    __syncthreads();   // only barrier in the kernel

    const int   slice = q * 8 + wid;
    const int   t0    = slice * TOKW;
    const float bias  = ba[0];

    const float* eb = emb + (size_t)s * T_TOK * BERT;
    const float* pb = pos + (size_t)s * T_TOK * POSD;

    float4 acc[6];
    #pragma unroll
    for (int i = 0; i < 6; i++) acc[i] = make_float4(0.f, 0.f, 0.f, 0.f);
    float m = -1e30f;
    float d = 0.f;

    #pragma unroll 1
    for (int j = 0; j < TOKW; j += 2) {
        const int t = t0 + j;

        float4 x0[7], x1[7];
        #pragma unroll
        for (int i = 0; i < 6; i++)
            x0[i] = *(const float4*)(eb + (size_t)t * BERT + i * 128 + lane * 4);
        x0[6] = *(const float4*)(pb + (size_t)t * POSD + lane * 4);
        #pragma unroll
        for (int i = 0; i < 6; i++)
            x1[i] = *(const float4*)(eb + (size_t)(t + 1) * BERT + i * 128 + lane * 4);
        x1[6] = *(const float4*)(pb + (size_t)(t + 1) * POSD + lane * 4);

        float p0 = 0.f, p1 = 0.f;
        #pragma unroll
        for (int i = 0; i < 7; i++) {
            const float4 wv = *(const float4*)(s_wa + i * 128 + lane * 4);
            p0 += x0[i].x * wv.x + x0[i].y * wv.y + x0[i].z * wv.z + x0[i].w * wv.w;
            p1 += x1[i].x * wv.x + x1[i].y * wv.y + x1[i].z * wv.z + x1[i].w * wv.w;
        }
        #pragma unroll
        for (int o = 16; o > 0; o >>= 1) {
            p0 += __shfl_xor_sync(0xffffffffu, p0, o);
            p1 += __shfl_xor_sync(0xffffffffu, p1, o);
        }

        const float a0    = p0 + bias;
        const float a1    = p1 + bias;
        const float m_new = fmaxf(m, fmaxf(a0, a1));
        const float scale = __expf(m - m_new);
        const float e0    = __expf(a0 - m_new);
        const float e1    = __expf(a1 - m_new);
        d = d * scale + e0 + e1;
        #pragma unroll
        for (int i = 0; i < 6; i++) {
            acc[i].x = acc[i].x * scale + e0 * x0[i].x + e1 * x1[i].x;
            acc[i].y = acc[i].y * scale + e0 * x0[i].y + e1 * x1[i].y;
            acc[i].z = acc[i].z * scale + e0 * x0[i].z + e1 * x1[i].z;
            acc[i].w = acc[i].w * scale + e0 * x0[i].w + e1 * x1[i].w;
        }
        m = m_new;
    }

    const int ps = slice * S_SEG + s;
    float* ob = g_pacc + (size_t)ps * BERT;
    #pragma unroll
    for (int i = 0; i < 6; i++)
        *(float4*)(ob + i * 128 + lane * 4) = acc[i];
    if (lane == 0) {
        g_pm[ps] = m;
        g_pd[ps] = d;
    }
}

// ---------------------------------------------------------------------------
// Kernel 1b: merge WSLICES=32 partials per segment (flash-attn merge).
// ---------------------------------------------------------------------------
__global__ __launch_bounds__(192)
void pool_merge_kernel()
{
    __shared__ float sm[WSLICES], sd[WSLICES], ssc[WSLICES];
    const int s   = blockIdx.x;
    const int tid = threadIdx.x;

    if (tid < WSLICES) {
        sm[tid] = g_pm[tid * S_SEG + s];
        sd[tid] = g_pd[tid * S_SEG + s];
    }
    __syncthreads();

    float M = -1e30f;
    #pragma unroll
    for (int z = 0; z < WSLICES; z++) M = fmaxf(M, sm[z]);

    if (tid < WSLICES) ssc[tid] = __expf(sm[tid] - M);
    __syncthreads();

    float D = 0.f;
    #pragma unroll
    for (int z = 0; z < WSLICES; z++) D += sd[z] * ssc[z];
    const float inv = 1.f / D;

    float4 acc = make_float4(0.f, 0.f, 0.f, 0.f);
    #pragma unroll 4
    for (int z = 0; z < WSLICES; z++) {
        const float  f = ssc[z];
        const float4 p = *(const float4*)(g_pacc + (size_t)(z * S_SEG + s) * BERT + 4 * tid);
        acc.x += f * p.x;
        acc.y += f * p.y;
        acc.z += f * p.z;
        acc.w += f * p.w;
    }
    float4 o = make_float4(acc.x * inv, acc.y * inv, acc.z * inv, acc.w * inv);
    *(float4*)(g_segvec + (size_t)s * BERT + 4 * tid) = o;
}

// ---------------------------------------------------------------------------
// Kernel 2: deterministic segment sum (sorted ids). One CTA per segment g.
// ---------------------------------------------------------------------------
__global__ __launch_bounds__(256)
void segsum_kernel(const int* __restrict__ seg)
{
    __shared__ int sid[S_SEG];
    const int g = blockIdx.x;
    const int tid = threadIdx.x;
    sid[tid] = seg[tid];
    __syncthreads();

    float a0 = 0.f, a1 = 0.f, a2 = 0.f;
    for (int s = 0; s < S_SEG; s++) {
        if (sid[s] == g) {
            const float* r = g_segvec + (size_t)s * BERT;
            a0 += r[tid];
            a1 += r[tid + 256];
            a2 += r[tid + 512];
        }
    }
    g_vecs[g * BERT + tid]       = a0;
    g_vecs[g * BERT + tid + 256] = a1;
    g_vecs[g * BERT + tid + 512] = a2;
}

// ---------------------------------------------------------------------------
// Kernels 3/4: split-K GEMM partials, cp.async-staged smem tiles.
// grid (16 colblocks, 2 rowblocks, KSLICES=32) = 1024 CTAs, 128 threads.
// CTA = 32 rows x 64 cols x CHUNK. All W+x loads issued async up front,
// one wait, then compute purely from smem.
// thread = (colquad q -> 4 cols, rowgroup r -> 4 rows).
// ---------------------------------------------------------------------------
template <int K>
__global__ __launch_bounds__(128)
void mlp_splitk_kernel(const float* __restrict__ in, const float* __restrict__ W,
                       float* __restrict__ part)
{
    constexpr int CHUNK = K / KSLICES;   // 24 or 32 (multiples of 8; *4B %16==0)
    constexpr int C4    = CHUNK / 4;     // float4s per x row
    __shared__ float ws[CHUNK * 64];     // W tile [kk][64]
    __shared__ float xs[32 * CHUNK];     // x tile [row][kk]

    const int tid   = threadIdx.x;
    const int q     = tid & 15;
    const int r     = tid >> 4;          // 0..7
    const int jbase = blockIdx.x * 64 + q * 4;
    const int rbase = blockIdx.y * 32;
    const int k0    = blockIdx.z * CHUNK;

    const uint32_t ws_u = (uint32_t)__cvta_generic_to_shared(ws);
    const uint32_t xs_u = (uint32_t)__cvta_generic_to_shared(xs);

    // async-stage W tile: CHUNK rows x 16 float4
    const float* wg = W + (size_t)k0 * H1 + blockIdx.x * 64;
    #pragma unroll
    for (int idx = tid; idx < CHUNK * 16; idx += 128) {
        const int kk = idx >> 4;
        const int cc = idx & 15;
        CP_ASYNC_16(ws_u + (uint32_t)(kk * 64 + cc * 4) * 4,
                    wg + (size_t)kk * H1 + cc * 4);
    }
    // async-stage x tile: 32 rows x C4 float4
    const float* xg = in + (size_t)rbase * K + k0;
    #pragma unroll
    for (int idx = tid; idx < 32 * C4; idx += 128) {
        const int rr = idx / C4;
        const int cc = idx - rr * C4;
        CP_ASYNC_16(xs_u + (uint32_t)(rr * CHUNK + cc * 4) * 4,
                    xg + (size_t)rr * K + cc * 4);
    }
    CP_ASYNC_WAIT_ALL();
    __syncthreads();

    float4 acc[4];
    #pragma unroll
    for (int i = 0; i < 4; i++) acc[i] = make_float4(0.f, 0.f, 0.f, 0.f);

    const float* xp = xs + (r * 4) * CHUNK;

    #pragma unroll 8
    for (int kk = 0; kk < CHUNK; kk++) {
        const float4 wv = *(const float4*)(ws + kk * 64 + q * 4);
        #pragma unroll
        for (int rr = 0; rr < 4; rr++) {
            const float xv = xp[rr * CHUNK + kk];
            acc[rr].x += xv * wv.x;
            acc[rr].y += xv * wv.y;
            acc[rr].z += xv * wv.z;
            acc[rr].w += xv * wv.w;
        }
    }

    float* pb = part + (size_t)blockIdx.z * NSEG * H1 + (size_t)(rbase + r * 4) * H1 + jbase;
    #pragma unroll
    for (int i = 0; i < 4; i++)
        *(float4*)(pb + (size_t)i * H1) = acc[i];
}

// Reduce partials + bias + LeakyReLU(0.01). grid 256 (quarter-row per CTA),
// 256 threads, one scalar column each. 32 independent loads per thread.
__global__ __launch_bounds__(256)
void mlp_reduce_kernel(const float* __restrict__ b, float* __restrict__ out)
{
    const int row = blockIdx.x >> 2;
    const int col = (blockIdx.x & 3) * 256 + threadIdx.x;
    const size_t off = (size_t)row * H1 + col;

    float a = 0.f;
    #pragma unroll
    for (int z = 0; z < KSLICES; z++)
        a += g_part[(size_t)z * NSEG * H1 + off];

    a += b[col];
    out[off] = a > 0.f ? a : 0.01f * a;
}

// ---------------------------------------------------------------------------
// Kernel 5: head (64,1024)@(1024,6) + bias, sigmoid. One warp per segment.
// ---------------------------------------------------------------------------
__global__ __launch_bounds__(32)
void head_kernel(const float* __restrict__ W3, const float* __restrict__ b3,
                 float* __restrict__ out)
{
    const int g    = blockIdx.x;
    const int lane = threadIdx.x;
    float p[NCLS] = {0.f, 0.f, 0.f, 0.f, 0.f, 0.f};

    for (int k = lane; k < H1; k += 32) {
        float x = g_h2[(size_t)g * H1 + k];
        #pragma unroll
        for (int j = 0; j < NCLS; j++)
            p[j] += x * W3[k * NCLS + j];
    }
    #pragma unroll
    for (int j = 0; j < NCLS; j++) {
        #pragma unroll
        for (int o = 16; o > 0; o >>= 1)
            p[j] += __shfl_xor_sync(0xffffffffu, p[j], o);
    }
    if (lane < NCLS) {
        float v = p[lane] + b3[lane];
        out[g * NCLS + lane] = 1.f / (1.f + expf(-v));
    }
}

// ---------------------------------------------------------------------------
extern "C" void kernel_launch(void* const* d_in, const int* in_sizes, int n_in,
                              void* d_out, int out_size)
{
    (void)in_sizes; (void)n_in; (void)out_size;
    const float* emb = (const float*)d_in[0];
    const float* pos = (const float*)d_in[1];
    const float* Wa  = (const float*)d_in[2];
    const float* ba  = (const float*)d_in[3];
    const float* W1  = (const float*)d_in[4];
    const float* b1  = (const float*)d_in[5];
    const float* W2  = (const float*)d_in[6];
    const float* b2  = (const float*)d_in[7];
    const float* W3  = (const float*)d_in[8];
    const float* b3  = (const float*)d_in[9];
    const int*   seg = (const int*)d_in[10];
    float* out = (float*)d_out;

    void *p_vecs = nullptr, *p_h1 = nullptr, *p_h2 = nullptr, *p_part = nullptr;
    cudaGetSymbolAddress(&p_vecs, g_vecs);
    cudaGetSymbolAddress(&p_h1, g_h1);
    cudaGetSymbolAddress(&p_h2, g_h2);
    cudaGetSymbolAddress(&p_part, g_part);

    pool_part_kernel<<<dim3(S_SEG, 4), 256>>>(emb, pos, Wa, ba);
    pool_merge_kernel<<<S_SEG, 192>>>();
    segsum_kernel<<<NSEG, 256>>>(seg);

    mlp_splitk_kernel<BERT><<<dim3(16, 2, KSLICES), 128>>>(
        (const float*)p_vecs, W1, (float*)p_part);
    mlp_reduce_kernel<<<NSEG * 4, 256>>>(b1, (float*)p_h1);

    mlp_splitk_kernel<H1><<<dim3(16, 2, KSLICES), 128>>>(
        (const float*)p_h1, W2, (float*)p_part);
    mlp_reduce_kernel<<<NSEG * 4, 256>>>(b2, (float*)p_h2);

    head_kernel<<<NSEG, 32>>>(W3, b3, out);
}